// round 16
// baseline (speedup 1.0000x reference)
#include <cuda_runtime.h>
#include <math.h>

#define CUTOFF   1.5f
#define NMAX     16384
#define NCCAP    15
#define NCELLS   (NCCAP*NCCAP*NCCAP)       // 3375
#define MAXC     160                        // flat candidates per cell
#define FBLK     128                        // 4 warps per block

// ---------------- device scratch (no allocations allowed) ----------------
__device__ float4       g_apos[NMAX];        // per-atom: xyz, w = spec + 8*cid
__device__ float4       g_cand[NCELLS*MAXC]; // flat shifted candidate lists
__device__ int          g_ccnt[NCELLS];      // MUST be zero at entry (reset at end)
__device__ float4       g_tbl[64];           // (1/sig, eps/alp, alp-1, eps/sig)
__device__ float        g_sig2[64];          // sig^2
__device__ float        g_part[4096];        // per-block energy partials
__device__ unsigned int g_arrive = 0u;       // phase-1 arrival counter
__device__ unsigned int g_release = 0u;      // phase-2 release flag
__device__ unsigned int g_done = 0u;         // end ticket

// =======================================================================
// ONE FUSED KERNEL.
// Phase 1: warp-per-atom — bin atom, scatter (with periodic shift) into
//          its 27 home-cell flat candidate lists. Block 0 builds tables.
// Grid barrier: arrive ticket + release flag (grid fully resident).
// Phase 2: warp-per-atom — coalesced sweep of the atom's dense candidate
//          list; warp reduce; per-block energy partial; last block
//          finalizes energy and resets scratch for graph replay.
// =======================================================================
__global__ void __launch_bounds__(FBLK) k_fused(
    const float* __restrict__ pos, const float* __restrict__ cell,
    const float* __restrict__ sig, const float* __restrict__ eps,
    const float* __restrict__ alp, const int* __restrict__ spec,
    float* __restrict__ out, int n, int S)
{
    __shared__ float4 s_tbl[64];
    __shared__ float  s_sig2[64];
    __shared__ float4 s_f[FBLK/32];
    __shared__ int    s_flag;

    int t = threadIdx.x, lane = t & 31, warp = t >> 5;

    // ---------------- phase 1: tables + scatter ----------------
    if (blockIdx.x == 0 && t < S*S) {
        float sg = sig[t], ep = eps[t], al = alp[t];
        g_tbl[t]  = make_float4(1.0f/sg, ep/al, al - 1.0f, ep/sg);
        g_sig2[t] = sg * sg;
    }

    int a = blockIdx.x * (FBLK/32) + warp;
    if (a < n) {
        // cell matrix + inverse (registers, redundant per lane)
        float c00=cell[0], c01=cell[1], c02=cell[2];
        float c10=cell[3], c11=cell[4], c12=cell[5];
        float c20=cell[6], c21=cell[7], c22=cell[8];
        float det = c00*(c11*c22 - c12*c21) - c01*(c10*c22 - c12*c20) + c02*(c10*c21 - c11*c20);
        float id = 1.0f / det;
        float i00=(c11*c22-c12*c21)*id, i01=(c02*c21-c01*c22)*id, i02=(c01*c12-c02*c11)*id;
        float i10=(c12*c20-c10*c22)*id, i11=(c00*c22-c02*c20)*id, i12=(c02*c10-c00*c12)*id;
        float i20=(c10*c21-c11*c20)*id, i21=(c01*c20-c00*c21)*id, i22=(c00*c11-c01*c10)*id;
        float w0 = rsqrtf(i00*i00 + i10*i10 + i20*i20);
        float w1 = rsqrtf(i01*i01 + i11*i11 + i21*i21);
        float w2 = rsqrtf(i02*i02 + i12*i12 + i22*i22);
        int n0 = (int)floorf(w0 / CUTOFF); n0 = n0 < 1 ? 1 : (n0 > NCCAP ? NCCAP : n0);
        int n1 = (int)floorf(w1 / CUTOFF); n1 = n1 < 1 ? 1 : (n1 > NCCAP ? NCCAP : n1);
        int n2 = (int)floorf(w2 / CUTOFF); n2 = n2 < 1 ? 1 : (n2 > NCCAP ? NCCAP : n2);

        float x = pos[3*a], y = pos[3*a+1], z = pos[3*a+2];
        float f0 = x*i00 + y*i10 + z*i20;
        float f1 = x*i01 + y*i11 + z*i21;
        float f2 = x*i02 + y*i12 + z*i22;
        f0 -= floorf(f0); f1 -= floorf(f1); f2 -= floorf(f2);
        int ax = (int)(f0 * (float)n0); ax = ax >= n0 ? n0-1 : (ax < 0 ? 0 : ax);
        int ay = (int)(f1 * (float)n1); ay = ay >= n1 ? n1-1 : (ay < 0 ? 0 : ay);
        int az = (int)(f2 * (float)n2); az = az >= n2 ? n2-1 : (az < 0 ? 0 : az);
        int cid = (az*n1 + ay)*n0 + ax;
        int sp = spec[a];

        if (lane == 13)   // center offset: record per-atom data
            g_apos[a] = make_float4(x, y, z, (float)(sp + 8*cid));

        if (lane < 27) {
            int dx = lane % 3 - 1, dy = (lane / 3) % 3 - 1, dz = lane / 9 - 1;
            int cx = ax + dx, wx = 0;
            int cy = ay + dy, wy = 0;
            int cz = az + dz, wz = 0;
            if (cx < 0) { cx += n0; wx = 1; } else if (cx >= n0) { cx -= n0; wx = -1; }
            if (cy < 0) { cy += n1; wy = 1; } else if (cy >= n1) { cy -= n1; wy = -1; }
            if (cz < 0) { cz += n2; wz = 1; } else if (cz >= n2) { cz -= n2; wz = -1; }
            int ct = (cz*n1 + cy)*n0 + cx;
            float shx = wx*c00 + wy*c10 + wz*c20;
            float shy = wx*c01 + wy*c11 + wz*c21;
            float shz = wx*c02 + wy*c12 + wz*c22;
            int slot = atomicAdd(&g_ccnt[ct], 1);
            if (slot < MAXC)
                g_cand[ct*MAXC + slot] = make_float4(x + shx, y + shy, z + shz, (float)sp);
        }
    }

    // ---------------- grid barrier (grid is fully resident) ----------------
    __syncthreads();
    if (t == 0) {
        __threadfence();                        // publish phase-1 writes
        unsigned int r = atomicAdd(&g_arrive, 1u);
        if (r == gridDim.x - 1) {
            atomicExch(&g_release, 1u);         // last arriver releases everyone
        }
        while (atomicAdd(&g_release, 0u) == 0u) // strong read; spin
            __nanosleep(64);
        __threadfence();                        // acquire
    }
    __syncthreads();

    // ---------------- phase 2: force ----------------
    if (t < S*S) { s_tbl[t] = g_tbl[t]; s_sig2[t] = g_sig2[t]; }
    __syncthreads();

    float fx = 0.f, fy = 0.f, fz = 0.f, en = 0.f;
    if (a < n) {
        float4 pa = g_apos[a];
        int w   = (int)pa.w;
        int si  = w & 7;
        int cid = w >> 3;
        int ntot = g_ccnt[cid];
        ntot = ntot > MAXC ? MAXC : ntot;
        int base = cid * MAXC;
        int sBase = si * S;

        for (int q = lane; q < ntot; q += 32) {
            float4 cb = g_cand[base + q];
            float dx = cb.x - pa.x;
            float dy = cb.y - pa.y;
            float dz = cb.z - pa.z;
            float r2 = fmaf(dx,dx, fmaf(dy,dy, dz*dz));
            int idx = sBase + (int)cb.w;
            // r2 < sig^2  <=>  1 - r/sig > 0  (implies r < cutoff); r2>eps skips self
            if (r2 < s_sig2[idx] && r2 > 1e-12f) {
                float rinv = rsqrtf(r2);
                float r = r2 * rinv;
                float4 tb = s_tbl[idx];
                float f = fmaf(-r, tb.x, 1.0f);          // 1 - r/sig
                float pw = __powf(f, tb.z);              // f^(alpha-1)
                en = fmaf(tb.y * f, pw, en);             // eps/alpha * f^alpha
                float coef = tb.w * pw * rinv;           // eps/sig * f^(a-1) / r
                fx = fmaf(-coef, dx, fx);
                fy = fmaf(-coef, dy, fy);
                fz = fmaf(-coef, dz, fz);
            }
        }
    }

    // warp reduction
    #pragma unroll
    for (int off = 16; off; off >>= 1) {
        fx += __shfl_down_sync(0xffffffffu, fx, off);
        fy += __shfl_down_sync(0xffffffffu, fy, off);
        fz += __shfl_down_sync(0xffffffffu, fz, off);
        en += __shfl_down_sync(0xffffffffu, en, off);
    }
    if (lane == 0) {
        if (a < n) {
            out[1 + 3*a + 0] = fx;
            out[1 + 3*a + 1] = fy;
            out[1 + 3*a + 2] = fz;
        }
        s_f[warp] = make_float4(0.f, 0.f, 0.f, (a < n) ? en : 0.f);
    }
    __syncthreads();

    if (t == 0) {
        float e = 0.f;
        #pragma unroll
        for (int w = 0; w < FBLK/32; w++) e += s_f[w].w;
        g_part[blockIdx.x] = e;
        __threadfence();
        unsigned int d = atomicAdd(&g_done, 1u);
        s_flag = (d == gridDim.x - 1) ? 1 : 0;
    }
    __syncthreads();

    // last block: reduce partials, write energy, reset ALL scratch state
    if (s_flag) {
        __threadfence();
        __shared__ float s_red[FBLK];
        int nb = gridDim.x;
        float acc = 0.f;
        for (int k = t; k < nb; k += FBLK) acc += g_part[k];
        s_red[t] = acc;
        __syncthreads();
        for (int o = FBLK/2; o > 0; o >>= 1) {
            if (t < o) s_red[t] += s_red[t + o];
            __syncthreads();
        }
        if (t == 0) {
            out[0] = 0.5f * s_red[0];
            g_arrive  = 0u;
            g_release = 0u;
            g_done    = 0u;
        }
        for (int k = t; k < NCELLS; k += FBLK) g_ccnt[k] = 0;
    }
}

// ---------------- launch ----------------
extern "C" void kernel_launch(void* const* d_in, const int* in_sizes, int n_in,
                              void* d_out, int out_size) {
    const float* pos  = (const float*)d_in[0];
    const float* cell = (const float*)d_in[1];
    const float* sig  = (const float*)d_in[2];
    const float* eps  = (const float*)d_in[3];
    const float* alp  = (const float*)d_in[4];
    const int*   spec = (const int*)  d_in[5];
    int n  = in_sizes[5];
    int ss = in_sizes[2];
    int S = 1; while (S*S < ss) S++;
    float* out = (float*)d_out;

    int blocks = (n + FBLK/32 - 1) / (FBLK/32);   // one warp per atom
    k_fused<<<blocks, FBLK>>>(pos, cell, sig, eps, alp, spec, out, n, S);
}